// round 15
// baseline (speedup 1.0000x reference)
#include <cuda_runtime.h>
#include <cuda_fp16.h>
#include <cstdint>

typedef unsigned int u32;
typedef unsigned long long u64;

#define THREADS 128
#define TILE_E 128

#define INV_SQRT3 0.5773502691896258f
#define INV_SQRT8 0.35355339059327373f
#define SCALE_OUT 0.022097086912079608f   // PATH_ALPHA / sqrt(HIDDEN)
#define INV_SQRT_MUL 0.25f

// ---- shared memory byte offsets (from 1024-aligned base) ----
#define OFF_A    0          // 128 rows x 128B (64 f16), swizzled  (16KB)
#define OFF_B    16384      // 2 x 16KB half-block buffers (32KB total)
#define OFF_S    49152      // float[6][128][17] = 52224
#define OFF_RAD  101376     // float[128][8]
#define OFF_W1   105472     // float[512]
#define OFF_ATTR 107520     // float[128][4]
#define OFF_DST  109568     // int[128]
#define OFF_SRC  110080     // int[128]
#define SMEM_BYTES (110592 + 1024)

#define SE_STR 17
#define SF_STR 2176        // 128*17

// W2 pre-transposed f16: [m(1024)][k(64)]  (B^T row-major)
__device__ __align__(16) __half g_w2t[1024 * 64];

// ---------------- PTX helpers ----------------
__device__ __forceinline__ u32 smem_u32(const void* p) {
    u32 a;
    asm("{ .reg .u64 t; cvta.to.shared.u64 t, %1; cvt.u32.u64 %0, t; }"
        : "=r"(a) : "l"(p));
    return a;
}
__device__ __forceinline__ u32 swz(u32 row, u32 kb) {
    return row * 128 + (kb ^ ((row & 7) << 4));
}
__device__ __forceinline__ void ldsm4(u32* r, u32 addr) {
    asm volatile("ldmatrix.sync.aligned.m8n8.x4.shared.b16 {%0,%1,%2,%3}, [%4];"
                 : "=r"(r[0]), "=r"(r[1]), "=r"(r[2]), "=r"(r[3]) : "r"(addr));
}
__device__ __forceinline__ void mma16816(float* d, const u32* a, const u32* b) {
    asm volatile("mma.sync.aligned.m16n8k16.row.col.f32.f16.f16.f32 "
                 "{%0,%1,%2,%3}, {%4,%5,%6,%7}, {%8,%9}, {%0,%1,%2,%3};"
                 : "+f"(d[0]), "+f"(d[1]), "+f"(d[2]), "+f"(d[3])
                 : "r"(a[0]), "r"(a[1]), "r"(a[2]), "r"(a[3]),
                   "r"(b[0]), "r"(b[1]));
}
__device__ __forceinline__ void cp16(u32 dst, const void* src) {
    asm volatile("cp.async.cg.shared.global [%0], [%1], 16;" :: "r"(dst), "l"(src));
}
#define CP_COMMIT() asm volatile("cp.async.commit_group;" ::: "memory")
#define CP_WAIT0()  asm volatile("cp.async.wait_group 0;" ::: "memory")
#define CP_WAIT1()  asm volatile("cp.async.wait_group 1;" ::: "memory")

typedef unsigned long long ull;
__device__ __forceinline__ ull pack2(float lo, float hi) {
    ull r; asm("mov.b64 %0, {%1, %2};" : "=l"(r) : "f"(lo), "f"(hi)); return r;
}
__device__ __forceinline__ ull splat2(float v) { return pack2(v, v); }
__device__ __forceinline__ void unpack2(ull v, float& lo, float& hi) {
    asm("mov.b64 {%0, %1}, %2;" : "=f"(lo), "=f"(hi) : "l"(v));
}
__device__ __forceinline__ ull fma2(ull a, ull b, ull c) {
    ull d; asm("fma.rn.f32x2 %0, %1, %2, %3;" : "=l"(d) : "l"(a), "l"(b), "l"(c)); return d;
}
__device__ __forceinline__ void red2(float* p, float a, float b) {
    asm volatile("red.global.add.v2.f32 [%0], {%1,%2};" :: "l"(p), "f"(a), "f"(b) : "memory");
}

#define PREP_BLOCKS 64

// ---------------- merged pre-kernel: W2 transpose + self-connection ----------------
__global__ void pre_kernel(const float* __restrict__ W2,
                           const float* __restrict__ x,
                           const float* __restrict__ L0,
                           const float* __restrict__ L1,
                           float* __restrict__ out,
                           int Nnodes)
{
    int blk = blockIdx.x;
    int t = threadIdx.x;
    if (blk < PREP_BLOCKS) {
        int i4 = blk * 256 + t;                 // 0..16383
        float4 v = reinterpret_cast<const float4*>(W2)[i4];
        int i = i4 * 4;
        int k = i >> 10, m = i & 1023;
        g_w2t[(m + 0) * 64 + k] = __float2half(v.x);
        g_w2t[(m + 1) * 64 + k] = __float2half(v.y);
        g_w2t[(m + 2) * 64 + k] = __float2half(v.z);
        g_w2t[(m + 3) * 64 + k] = __float2half(v.w);
        return;
    }

    __shared__ float l0[256], l1[256];
    l0[t] = L0[t];
    l1[t] = L1[t];
    __syncthreads();

    int n = (blk - PREP_BLOCKS) * blockDim.x + t;
    if (n >= Nnodes) return;

    float xv[64];
    const float4* xr = reinterpret_cast<const float4*>(x + (size_t)n * 64);
    #pragma unroll
    for (int i = 0; i < 16; i++) {
        float4 v = xr[i];
        xv[4 * i + 0] = v.x; xv[4 * i + 1] = v.y;
        xv[4 * i + 2] = v.z; xv[4 * i + 3] = v.w;
    }

    float* orow = out + (size_t)n * 64;
    #pragma unroll
    for (int v = 0; v < 16; v++) {
        float s = 0.f;
        #pragma unroll
        for (int u = 0; u < 16; u++) s += xv[u] * l0[u * 16 + v];
        orow[v] = INV_SQRT_MUL * s;
    }
    #pragma unroll
    for (int v = 0; v < 16; v++) {
        float sk0 = 0.f, sk1 = 0.f, sk2 = 0.f;
        #pragma unroll
        for (int u = 0; u < 16; u++) {
            float L = l1[u * 16 + v];
            sk0 += xv[16 + 3 * u + 0] * L;
            sk1 += xv[16 + 3 * u + 1] * L;
            sk2 += xv[16 + 3 * u + 2] * L;
        }
        orow[16 + 3 * v + 0] = INV_SQRT_MUL * sk0;
        orow[16 + 3 * v + 1] = INV_SQRT_MUL * sk1;
        orow[16 + 3 * v + 2] = INV_SQRT_MUL * sk2;
    }
}

// ---------------- B half staging: phase ph (0..7) -> buffer ph&1 ----------------
__device__ __forceinline__ void prefetchBH(u32 sbase, int ph, int tid) {
    const char* g = (const char*)g_w2t + (size_t)ph * 16384;
    u32 d = sbase + OFF_B + (u32)((ph & 1) * 16384);
    #pragma unroll
    for (int it = 0; it < 8; it++) {
        int i = tid + it * THREADS;           // 0..1023 16B chunks
        u32 row = (u32)(i >> 3), c16 = (u32)((i & 7) * 16);
        cp16(d + swz(row, c16), g + (size_t)i * 16);
    }
    CP_COMMIT();
}

// load one 16x16 (n-rows x k) B fragment group: dst[kt 0..3][2]
__device__ __forceinline__ void ldB(u32 dst[4][2], u32 base, u32 nrow,
                                    u32 brow_r, u32 bkb_g) {
    #pragma unroll
    for (int h = 0; h < 2; h++) {
        u32 t[4];
        ldsm4(t, base + swz(nrow + brow_r, (u32)h * 64 + bkb_g));
        dst[2*h][0] = t[0]; dst[2*h][1] = t[1];
        dst[2*h+1][0] = t[2]; dst[2*h+1][1] = t[3];
    }
}

// ---------------- main edge kernel: 4 warps, 32 edges/warp ----------------
__global__ void __launch_bounds__(THREADS, 2)
edge_mma_kernel(const float* __restrict__ x,
                const float* __restrict__ edge_attr,
                const float* __restrict__ edge_len,
                const int* __restrict__ src,
                const int* __restrict__ dst,
                const float* __restrict__ W1,
                float* __restrict__ out,
                int E)
{
    extern __shared__ char smem_raw[];
    char* smem = (char*)((((size_t)smem_raw) + 1023) & ~(size_t)1023);
    const u32 sbase = smem_u32(smem);
    const int tid = threadIdx.x;
    const int wid = tid >> 5;
    const int lane = tid & 31;
    const int e_base = blockIdx.x * TILE_E;

    float* w1s  = (float*)(smem + OFF_W1);
    float* attr = (float*)(smem + OFF_ATTR);
    int*   dsts = (int*)(smem + OFF_DST);
    int*   srcs = (int*)(smem + OFF_SRC);
    float* rad  = (float*)(smem + OFF_RAD);
    float* Sf   = (float*)(smem + OFF_S);

    for (int i = tid; i < 512; i += THREADS) w1s[i] = W1[i];

    {
        int e = e_base + tid;
        int ec = e < E ? e : E - 1;      // clamp; epilogue predicates
        srcs[tid] = src[ec];
        dsts[tid] = dst[ec];
        float len = edge_len[ec];
        float4 a = reinterpret_cast<const float4*>(edge_attr)[ec];
        attr[tid * 4 + 0] = a.x; attr[tid * 4 + 1] = a.y;
        attr[tid * 4 + 2] = a.z; attr[tid * 4 + 3] = a.w;
        #pragma unroll
        for (int r = 0; r < 8; r++) {
            float d = len - (5.0f / 7.0f) * (float)r;
            rad[tid * 8 + r] = __expf(-0.5f * d * d);
        }
    }
    __syncthreads();

    const u32 xstage = sbase + OFF_B + 16384;   // buffer 1 doubles as x staging

    // G1: stage x rows for edges 0..63 (coalesced)
    #pragma unroll
    for (int it = 0; it < 8; it++) {
        int i = tid + it * THREADS;       // 0..1023
        int el = i >> 4, q = i & 15;
        cp16(xstage + (u32)(el * 256 + q * 16), x + (size_t)srcs[el] * 64 + q * 4);
    }
    CP_COMMIT();
    // G2: B block0 half0 -> buffer 0
    prefetchBH(sbase, 0, tid);

    // ---- h = silu(radial @ W1 / sqrt(8)) -> f16 A tile (overlaps staging) ----
    for (int i = tid; i < TILE_E * 64; i += THREADS) {
        int e = i >> 6, j = i & 63;
        float s = 0.f;
        #pragma unroll
        for (int r = 0; r < 8; r++) s += rad[e * 8 + r] * w1s[r * 64 + j];
        s *= INV_SQRT8;
        float hv = s / (1.0f + __expf(-s));
        *reinterpret_cast<__half*>(smem + OFF_A + swz((u32)e, (u32)(j * 2))) =
            __float2half(hv);
    }

    CP_WAIT1();          // G1 done; G2 may still stream
    __syncthreads();

    // ---- S build pass 1 (edges 0..63) ----
    {
        const float* raw = (const float*)(smem + OFF_B + 16384);
        #pragma unroll
        for (int it = 0; it < 8; it++) {
            int i = tid + it * THREADS;
            int u = i & 15, el = i >> 4;
            const float* xr = raw + el * 64;
            float x0  = xr[u];
            float x10 = xr[16 + 3 * u + 0];
            float x11 = xr[16 + 3 * u + 1];
            float x12 = xr[16 + 3 * u + 2];
            float sh0 = attr[el * 4 + 0];
            float a1 = attr[el * 4 + 1], a2 = attr[el * 4 + 2], a3 = attr[el * 4 + 3];
            float* sp = Sf + el * SE_STR + u;
            sp[0 * SF_STR] = sh0 * x0;
            sp[1 * SF_STR] = INV_SQRT3 * (x10 * a1 + x11 * a2 + x12 * a3);
            sp[2 * SF_STR] = x0;
            sp[3 * SF_STR] = sh0 * x10;
            sp[4 * SF_STR] = sh0 * x11;
            sp[5 * SF_STR] = sh0 * x12;
        }
    }
    __syncthreads();

    // G3: stage x rows for edges 64..127
    #pragma unroll
    for (int it = 0; it < 8; it++) {
        int i = tid + it * THREADS;
        int el = i >> 4, q = i & 15;
        cp16(xstage + (u32)(el * 256 + q * 16), x + (size_t)srcs[64 + el] * 64 + q * 4);
    }
    CP_COMMIT();
    CP_WAIT0();          // G2 + G3 done
    __syncthreads();

    // ---- S build pass 2 (edges 64..127) ----
    {
        const float* raw = (const float*)(smem + OFF_B + 16384);
        #pragma unroll
        for (int it = 0; it < 8; it++) {
            int i = tid + it * THREADS;
            int u = i & 15, el = i >> 4;
            int e = 64 + el;
            const float* xr = raw + el * 64;
            float x0  = xr[u];
            float x10 = xr[16 + 3 * u + 0];
            float x11 = xr[16 + 3 * u + 1];
            float x12 = xr[16 + 3 * u + 2];
            float sh0 = attr[e * 4 + 0];
            float a1 = attr[e * 4 + 1], a2 = attr[e * 4 + 2], a3 = attr[e * 4 + 3];
            float* sp = Sf + e * SE_STR + u;
            sp[0 * SF_STR] = sh0 * x0;
            sp[1 * SF_STR] = INV_SQRT3 * (x10 * a1 + x11 * a2 + x12 * a3);
            sp[2 * SF_STR] = x0;
            sp[3 * SF_STR] = sh0 * x10;
            sp[4 * SF_STR] = sh0 * x11;
            sp[5 * SF_STR] = sh0 * x12;
        }
    }
    __syncthreads();     // buffer 1 free; S complete

    prefetchBH(sbase, 1, tid);    // B block0 half1 -> buffer 1

    // ---- preload A fragments: 2 tiles (32 rows) x 4 k-tiles ----
    u32 Af[2][4][4];
    {
        u32 grp = (u32)(lane >> 3), r = (u32)(lane & 7);
        u32 akb = (grp >> 1) * 16;
        #pragma unroll
        for (int at = 0; at < 2; at++) {
            u32 arow = (u32)(wid * 32 + at * 16) + r + (grp & 1) * 8;
            #pragma unroll
            for (int kt = 0; kt < 4; kt++)
                ldsm4(Af[at][kt], sbase + OFF_A + swz(arow, akb + (u32)kt * 32));
        }
    }

    // accumulators: [fam 0..4][edge 0..3][vpair 0..1] as f32x2
    ull acc[5][4][2];
    #pragma unroll
    for (int f = 0; f < 5; f++)
        #pragma unroll
        for (int e = 0; e < 4; e++) { acc[f][e][0] = 0ull; acc[f][e][1] = 0ull; }

    const int eoff = wid * 32 + (lane >> 2);   // e0 local index (e: +0,+8,+16,+24)
    const u32 brow_r = (u32)(lane & 7);
    const u32 bkb_g  = (u32)((lane >> 3) * 16);

    // ---- 8-phase pipelined mainloop (phase = block*2 + half, 128 n-rows each) ----
    #pragma unroll
    for (int p = 0; p < 8; p++) {
        if (p >= 1) {
            if (p == 7) { CP_WAIT0(); } else { CP_WAIT1(); }
            __syncthreads();   // buffer (p&1) ready & visible
        }
        const int b = p >> 1;
        const int half = p & 1;
        const u32 bbase = sbase + OFF_B + (u32)(half * 16384);

        #pragma unroll
        for (int ntq = 0; ntq < 4; ntq++) {
            u32 Bf[4][4][2];
            #pragma unroll
            for (int ch = 0; ch < 4; ch++)
                ldB(Bf[ch], bbase, (u32)(32 * ntq + 8 * ch), brow_r, bkb_g);

            float c[2][4][4];
            #pragma unroll
            for (int at = 0; at < 2; at++)
                #pragma unroll
                for (int ch = 0; ch < 4; ch++)
                    { c[at][ch][0] = 0.f; c[at][ch][1] = 0.f; c[at][ch][2] = 0.f; c[at][ch][3] = 0.f; }
            #pragma unroll
            for (int kt = 0; kt < 4; kt++)
                #pragma unroll
                for (int at = 0; at < 2; at++)
                    #pragma unroll
                    for (int ch = 0; ch < 4; ch++)
                        mma16816(c[at][ch], Af[at][kt], Bf[ch][kt]);

            #pragma unroll
            for (int uu = 0; uu < 2; uu++) {
                const int u = half * 8 + 2 * ntq + uu;
                if (b == 0 || b == 1) {
                    const float* sp = &Sf[b * SF_STR + eoff * SE_STR + u];
                    #pragma unroll
                    for (int e = 0; e < 4; e++) {
                        const int at = e >> 1, i = e & 1;
                        const float* d0 = c[at][2 * uu];
                        const float* d1 = c[at][2 * uu + 1];
                        ull s = splat2(sp[e * 8 * SE_STR]);
                        acc[0][e][0] = fma2(s, pack2(d0[2*i], d0[2*i+1]), acc[0][e][0]);
                        acc[0][e][1] = fma2(s, pack2(d1[2*i], d1[2*i+1]), acc[0][e][1]);
                    }
                } else if (b == 2) {
                    const float* sp = &Sf[2 * SF_STR + eoff * SE_STR + u];
                    #pragma unroll
                    for (int e = 0; e < 4; e++) {
                        const int at = e >> 1, i = e & 1;
                        const float* d0 = c[at][2 * uu];
                        const float* d1 = c[at][2 * uu + 1];
                        ull s = splat2(sp[e * 8 * SE_STR]);
                        acc[1][e][0] = fma2(s, pack2(d0[2*i], d0[2*i+1]), acc[1][e][0]);
                        acc[1][e][1] = fma2(s, pack2(d1[2*i], d1[2*i+1]), acc[1][e][1]);
                    }
                } else {
                    #pragma unroll
                    for (int k = 0; k < 3; k++) {
                        const float* sp = &Sf[(3 + k) * SF_STR + eoff * SE_STR + u];
                        #pragma unroll
                        for (int e = 0; e < 4; e++) {
                            const int at = e >> 1, i = e & 1;
                            const float* d0 = c[at][2 * uu];
                            const float* d1 = c[at][2 * uu + 1];
                            ull s = splat2(sp[e * 8 * SE_STR]);
                            acc[2+k][e][0] = fma2(s, pack2(d0[2*i], d0[2*i+1]), acc[2+k][e][0]);
                            acc[2+k][e][1] = fma2(s, pack2(d1[2*i], d1[2*i+1]), acc[2+k][e][1]);
                        }
                    }
                }
            }
        }

        if (p < 6) {
            __syncthreads();              // all warps done reading buffer (p&1)
            prefetchBH(sbase, p + 2, tid);
        }
    }

    // ---- epilogue: scatter-add via vector reds ----
    const int q = lane & 3;
    #pragma unroll
    for (int e = 0; e < 4; e++) {
        const int el = eoff + 8 * e;
        const int eg = e_base + el;
        if (eg >= E) continue;
        float* op = out + (size_t)dsts[el] * 64;
        const float k0 = attr[el * 4 + 1];
        const float k1 = attr[el * 4 + 2];
        const float k2 = attr[el * 4 + 3];

        #pragma unroll
        for (int p = 0; p < 2; p++) {
            float m0a, m0b, ta, tb;
            float a0a, a0b, a1a, a1b, a2a, a2b;
            unpack2(acc[0][e][p], m0a, m0b);
            unpack2(acc[1][e][p], ta, tb);
            unpack2(acc[2][e][p], a0a, a0b);
            unpack2(acc[3][e][p], a1a, a1b);
            unpack2(acc[4][e][p], a2a, a2b);
            const int v = 8 * p + 2 * q;
            red2(op + v, SCALE_OUT * m0a, SCALE_OUT * m0b);
            const int base = 16 + 3 * v;
            red2(op + base,     SCALE_OUT * fmaf(k0, ta, a0a), SCALE_OUT * fmaf(k1, ta, a1a));
            red2(op + base + 2, SCALE_OUT * fmaf(k2, ta, a2a), SCALE_OUT * fmaf(k0, tb, a0b));
            red2(op + base + 4, SCALE_OUT * fmaf(k1, tb, a1b), SCALE_OUT * fmaf(k2, tb, a2b));
        }
    }
}

extern "C" void kernel_launch(void* const* d_in, const int* in_sizes, int n_in,
                              void* d_out, int out_size)
{
    const float* x         = (const float*)d_in[0];
    const float* edge_attr = (const float*)d_in[1];
    const float* edge_len  = (const float*)d_in[2];
    const int*   src       = (const int*)d_in[3];
    const int*   dst       = (const int*)d_in[4];
    const float* W1        = (const float*)d_in[5];
    const float* W2        = (const float*)d_in[6];
    const float* L0        = (const float*)d_in[7];
    const float* L1        = (const float*)d_in[8];
    float* out = (float*)d_out;

    const int E = in_sizes[2];
    const int Nnodes = in_sizes[0] / 64;

    cudaFuncSetAttribute(edge_mma_kernel, cudaFuncAttributeMaxDynamicSharedMemorySize, SMEM_BYTES);

    const int sc_blocks = (Nnodes + 255) / 256;
    pre_kernel<<<PREP_BLOCKS + sc_blocks, 256>>>(W2, x, L0, L1, out, Nnodes);
    edge_mma_kernel<<<(E + TILE_E - 1) / TILE_E, THREADS, SMEM_BYTES>>>(
        x, edge_attr, edge_len, src, dst, W1, out, E);
}

// round 16
// speedup vs baseline: 1.1106x; 1.1106x over previous
#include <cuda_runtime.h>
#include <cuda_fp16.h>
#include <cstdint>

typedef unsigned int u32;
typedef unsigned long long u64;

#define THREADS 256
#define TILE_E 128

#define INV_SQRT3 0.5773502691896258f
#define INV_SQRT8 0.35355339059327373f
#define SCALE_OUT 0.022097086912079608f   // PATH_ALPHA / sqrt(HIDDEN)
#define INV_SQRT_MUL 0.25f

// ---- shared memory byte offsets (from 1024-aligned base) ----
#define OFF_A    0          // 128 rows x 128B (64 f16), swizzled  (16KB)
#define OFF_B    16384      // 2 x 16KB half-block buffers (32KB total)
#define OFF_S    49152      // float[6][128][17] = 52224
#define OFF_RAD  101376     // float[128][8]
#define OFF_W1   105472     // float[512]
#define OFF_ATTR 107520     // float[128][4]
#define OFF_DST  109568     // int[128]
#define OFF_SRC  110080     // int[128]
#define SMEM_BYTES (110592 + 1024)

#define SE_STR 17
#define SF_STR 2176        // 128*17

// W2 pre-transposed f16: [m(1024)][k(64)]  (B^T row-major)
__device__ __align__(16) __half g_w2t[1024 * 64];

// ---------------- PTX helpers ----------------
__device__ __forceinline__ u32 smem_u32(const void* p) {
    u32 a;
    asm("{ .reg .u64 t; cvta.to.shared.u64 t, %1; cvt.u32.u64 %0, t; }"
        : "=r"(a) : "l"(p));
    return a;
}
__device__ __forceinline__ u32 swz(u32 row, u32 kb) {
    return row * 128 + (kb ^ ((row & 7) << 4));
}
__device__ __forceinline__ void ldsm4(u32* r, u32 addr) {
    asm volatile("ldmatrix.sync.aligned.m8n8.x4.shared.b16 {%0,%1,%2,%3}, [%4];"
                 : "=r"(r[0]), "=r"(r[1]), "=r"(r[2]), "=r"(r[3]) : "r"(addr));
}
__device__ __forceinline__ void mma16816(float* d, const u32* a, const u32* b) {
    asm volatile("mma.sync.aligned.m16n8k16.row.col.f32.f16.f16.f32 "
                 "{%0,%1,%2,%3}, {%4,%5,%6,%7}, {%8,%9}, {%0,%1,%2,%3};"
                 : "+f"(d[0]), "+f"(d[1]), "+f"(d[2]), "+f"(d[3])
                 : "r"(a[0]), "r"(a[1]), "r"(a[2]), "r"(a[3]),
                   "r"(b[0]), "r"(b[1]));
}
__device__ __forceinline__ void cp16(u32 dst, const void* src) {
    asm volatile("cp.async.cg.shared.global [%0], [%1], 16;" :: "r"(dst), "l"(src));
}
#define CP_COMMIT() asm volatile("cp.async.commit_group;" ::: "memory")
#define CP_WAIT0()  asm volatile("cp.async.wait_group 0;" ::: "memory")
#define CP_WAIT1()  asm volatile("cp.async.wait_group 1;" ::: "memory")

typedef unsigned long long ull;
__device__ __forceinline__ ull pack2(float lo, float hi) {
    ull r; asm("mov.b64 %0, {%1, %2};" : "=l"(r) : "f"(lo), "f"(hi)); return r;
}
__device__ __forceinline__ ull splat2(float v) { return pack2(v, v); }
__device__ __forceinline__ void unpack2(ull v, float& lo, float& hi) {
    asm("mov.b64 {%0, %1}, %2;" : "=f"(lo), "=f"(hi) : "l"(v));
}
__device__ __forceinline__ ull fma2(ull a, ull b, ull c) {
    ull d; asm("fma.rn.f32x2 %0, %1, %2, %3;" : "=l"(d) : "l"(a), "l"(b), "l"(c)); return d;
}
__device__ __forceinline__ void red2(float* p, float a, float b) {
    asm volatile("red.global.add.v2.f32 [%0], {%1,%2};" :: "l"(p), "f"(a), "f"(b) : "memory");
}

#define PREP_BLOCKS 64

// ---------------- merged pre-kernel: W2 transpose + self-connection ----------------
__global__ void pre_kernel(const float* __restrict__ W2,
                           const float* __restrict__ x,
                           const float* __restrict__ L0,
                           const float* __restrict__ L1,
                           float* __restrict__ out,
                           int Nnodes)
{
    int blk = blockIdx.x;
    int t = threadIdx.x;
    if (blk < PREP_BLOCKS) {
        int i4 = blk * 256 + t;                 // 0..16383
        float4 v = reinterpret_cast<const float4*>(W2)[i4];
        int i = i4 * 4;
        int k = i >> 10, m = i & 1023;
        g_w2t[(m + 0) * 64 + k] = __float2half(v.x);
        g_w2t[(m + 1) * 64 + k] = __float2half(v.y);
        g_w2t[(m + 2) * 64 + k] = __float2half(v.z);
        g_w2t[(m + 3) * 64 + k] = __float2half(v.w);
        return;
    }

    __shared__ float l0[256], l1[256];
    l0[t] = L0[t];
    l1[t] = L1[t];
    __syncthreads();

    int n = (blk - PREP_BLOCKS) * blockDim.x + t;
    if (n >= Nnodes) return;

    float xv[64];
    const float4* xr = reinterpret_cast<const float4*>(x + (size_t)n * 64);
    #pragma unroll
    for (int i = 0; i < 16; i++) {
        float4 v = xr[i];
        xv[4 * i + 0] = v.x; xv[4 * i + 1] = v.y;
        xv[4 * i + 2] = v.z; xv[4 * i + 3] = v.w;
    }

    float* orow = out + (size_t)n * 64;
    #pragma unroll
    for (int v = 0; v < 16; v++) {
        float s = 0.f;
        #pragma unroll
        for (int u = 0; u < 16; u++) s += xv[u] * l0[u * 16 + v];
        orow[v] = INV_SQRT_MUL * s;
    }
    #pragma unroll
    for (int v = 0; v < 16; v++) {
        float sk0 = 0.f, sk1 = 0.f, sk2 = 0.f;
        #pragma unroll
        for (int u = 0; u < 16; u++) {
            float L = l1[u * 16 + v];
            sk0 += xv[16 + 3 * u + 0] * L;
            sk1 += xv[16 + 3 * u + 1] * L;
            sk2 += xv[16 + 3 * u + 2] * L;
        }
        orow[16 + 3 * v + 0] = INV_SQRT_MUL * sk0;
        orow[16 + 3 * v + 1] = INV_SQRT_MUL * sk1;
        orow[16 + 3 * v + 2] = INV_SQRT_MUL * sk2;
    }
}

// ---------------- B half staging: phase ph (0..7) -> buffer ph&1 ----------------
__device__ __forceinline__ void prefetchBH(u32 sbase, int ph, int tid) {
    const char* g = (const char*)g_w2t + (size_t)ph * 16384;
    u32 d = sbase + OFF_B + (u32)((ph & 1) * 16384);
    #pragma unroll
    for (int it = 0; it < 4; it++) {
        int i = tid + it * THREADS;           // 0..1023 16B chunks
        u32 row = (u32)(i >> 3), c16 = (u32)((i & 7) * 16);
        cp16(d + swz(row, c16), g + (size_t)i * 16);
    }
    CP_COMMIT();
}

// load one B fragment group: dst[kt 0..3][2]
__device__ __forceinline__ void ldB(u32 dst[4][2], u32 base, u32 nrow,
                                    u32 brow_r, u32 bkb_g) {
    #pragma unroll
    for (int h = 0; h < 2; h++) {
        u32 t[4];
        ldsm4(t, base + swz(nrow + brow_r, (u32)h * 64 + bkb_g));
        dst[2*h][0] = t[0]; dst[2*h][1] = t[1];
        dst[2*h+1][0] = t[2]; dst[2*h+1][1] = t[3];
    }
}

// ---------------- main edge kernel: persistent, grid-stride over tiles ----------------
__global__ void __launch_bounds__(THREADS, 2)
edge_mma_kernel(const float* __restrict__ x,
                const float* __restrict__ edge_attr,
                const float* __restrict__ edge_len,
                const int* __restrict__ src,
                const int* __restrict__ dst,
                const float* __restrict__ W1,
                float* __restrict__ out,
                int E, int ntiles)
{
    extern __shared__ char smem_raw[];
    char* smem = (char*)((((size_t)smem_raw) + 1023) & ~(size_t)1023);
    const u32 sbase = smem_u32(smem);
    const int tid = threadIdx.x;
    const int wid = tid >> 5;
    const int lane = tid & 31;

    float* w1s  = (float*)(smem + OFF_W1);
    float* attr = (float*)(smem + OFF_ATTR);
    int*   dsts = (int*)(smem + OFF_DST);
    int*   srcs = (int*)(smem + OFF_SRC);
    float* rad  = (float*)(smem + OFF_RAD);
    float* Sf   = (float*)(smem + OFF_S);

    for (int i = tid; i < 512; i += THREADS) w1s[i] = W1[i];

    const u32 xstage = sbase + OFF_B + 16384;   // buffer 1 doubles as x staging
    const int eoff = wid * 16 + (lane >> 2);    // e0 local index
    const u32 brow_r = (u32)(lane & 7);
    const u32 bkb_g  = (u32)((lane >> 3) * 16);
    const int q = lane & 3;

    for (int tile = blockIdx.x; tile < ntiles; tile += gridDim.x) {
        const int e_base = tile * TILE_E;
        __syncthreads();   // previous tile fully done (smem + buf reads)

        if (tid < TILE_E) {
            int e = e_base + tid;
            int ec = e < E ? e : E - 1;      // clamp; epilogue predicates
            srcs[tid] = src[ec];
            dsts[tid] = dst[ec];
            float len = edge_len[ec];
            float4 a = reinterpret_cast<const float4*>(edge_attr)[ec];
            attr[tid * 4 + 0] = a.x; attr[tid * 4 + 1] = a.y;
            attr[tid * 4 + 2] = a.z; attr[tid * 4 + 3] = a.w;
            #pragma unroll
            for (int r = 0; r < 8; r++) {
                float d = len - (5.0f / 7.0f) * (float)r;
                rad[tid * 8 + r] = __expf(-0.5f * d * d);
            }
        }
        __syncthreads();

        // G1: stage x rows for edges 0..63 (coalesced)
        #pragma unroll
        for (int it = 0; it < 4; it++) {
            int i = tid + it * THREADS;       // 0..1023
            int el = i >> 4, qq = i & 15;
            cp16(xstage + (u32)(el * 256 + qq * 16), x + (size_t)srcs[el] * 64 + qq * 4);
        }
        CP_COMMIT();
        // G2: B phase0 -> buffer 0 (streams during prologue)
        prefetchBH(sbase, 0, tid);

        // ---- h = silu(radial @ W1 / sqrt(8)) -> f16 A tile ----
        for (int i = tid; i < TILE_E * 64; i += THREADS) {
            int e = i >> 6, j = i & 63;
            float s = 0.f;
            #pragma unroll
            for (int r = 0; r < 8; r++) s += rad[e * 8 + r] * w1s[r * 64 + j];
            s *= INV_SQRT8;
            float hv = s / (1.0f + __expf(-s));
            *reinterpret_cast<__half*>(smem + OFF_A + swz((u32)e, (u32)(j * 2))) =
                __float2half(hv);
        }

        CP_WAIT1();          // G1 done; G2 may still stream
        __syncthreads();

        // ---- S build pass 1 (edges 0..63) ----
        {
            const float* raw = (const float*)(smem + OFF_B + 16384);
            #pragma unroll
            for (int it = 0; it < 4; it++) {
                int i = tid + it * THREADS;
                int u = i & 15, el = i >> 4;
                const float* xr = raw + el * 64;
                float x0  = xr[u];
                float x10 = xr[16 + 3 * u + 0];
                float x11 = xr[16 + 3 * u + 1];
                float x12 = xr[16 + 3 * u + 2];
                float sh0 = attr[el * 4 + 0];
                float a1 = attr[el * 4 + 1], a2 = attr[el * 4 + 2], a3 = attr[el * 4 + 3];
                float* sp = Sf + el * SE_STR + u;
                sp[0 * SF_STR] = sh0 * x0;
                sp[1 * SF_STR] = INV_SQRT3 * (x10 * a1 + x11 * a2 + x12 * a3);
                sp[2 * SF_STR] = x0;
                sp[3 * SF_STR] = sh0 * x10;
                sp[4 * SF_STR] = sh0 * x11;
                sp[5 * SF_STR] = sh0 * x12;
            }
        }
        __syncthreads();

        // G3: stage x rows for edges 64..127
        #pragma unroll
        for (int it = 0; it < 4; it++) {
            int i = tid + it * THREADS;
            int el = i >> 4, qq = i & 15;
            cp16(xstage + (u32)(el * 256 + qq * 16), x + (size_t)srcs[64 + el] * 64 + qq * 4);
        }
        CP_COMMIT();
        CP_WAIT0();          // G2 + G3 done
        __syncthreads();

        // ---- S build pass 2 (edges 64..127) ----
        {
            const float* raw = (const float*)(smem + OFF_B + 16384);
            #pragma unroll
            for (int it = 0; it < 4; it++) {
                int i = tid + it * THREADS;
                int u = i & 15, el = i >> 4;
                int e = 64 + el;
                const float* xr = raw + el * 64;
                float x0  = xr[u];
                float x10 = xr[16 + 3 * u + 0];
                float x11 = xr[16 + 3 * u + 1];
                float x12 = xr[16 + 3 * u + 2];
                float sh0 = attr[e * 4 + 0];
                float a1 = attr[e * 4 + 1], a2 = attr[e * 4 + 2], a3 = attr[e * 4 + 3];
                float* sp = Sf + e * SE_STR + u;
                sp[0 * SF_STR] = sh0 * x0;
                sp[1 * SF_STR] = INV_SQRT3 * (x10 * a1 + x11 * a2 + x12 * a3);
                sp[2 * SF_STR] = x0;
                sp[3 * SF_STR] = sh0 * x10;
                sp[4 * SF_STR] = sh0 * x11;
                sp[5 * SF_STR] = sh0 * x12;
            }
        }

        // ---- preload A fragments (4 k-tiles) ----
        u32 Af[4][4];
        {
            u32 grp = (u32)(lane >> 3), r = (u32)(lane & 7);
            u32 arow = (u32)(wid * 16) + r + (grp & 1) * 8;
            u32 akb  = (grp >> 1) * 16;
            #pragma unroll
            for (int kt = 0; kt < 4; kt++)
                ldsm4(Af[kt], sbase + OFF_A + swz(arow, akb + (u32)kt * 32));
        }

        // accumulators: [fam 0..4][edge 0..1][vpair 0..1] as f32x2
        ull acc[5][2][2];
        #pragma unroll
        for (int f = 0; f < 5; f++)
            #pragma unroll
            for (int e = 0; e < 2; e++) { acc[f][e][0] = 0ull; acc[f][e][1] = 0ull; }

        __syncthreads();     // S complete; buffer 1 free (x reads done)

        // ---- 8-phase mainloop, ONE barrier per phase ----
        // At phase-start barrier the other buffer is free -> prefetch p+1 there.
        #pragma unroll
        for (int p = 0; p < 8; p++) {
            if (p > 0) {
                CP_WAIT0();      // BH(p) landed
                __syncthreads(); // phase p-1 reads of buffer (p&1)^1... and (p&1) writers visible
            }
            if (p < 7) prefetchBH(sbase, p + 1, tid);   // into free buffer (p+1)&1

            const int b = p >> 1;
            const int half = p & 1;
            const u32 bbase = sbase + OFF_B + (u32)(half * 16384);

            #pragma unroll
            for (int ntq = 0; ntq < 4; ntq++) {
                u32 Bf[4][4][2];
                #pragma unroll
                for (int ch = 0; ch < 4; ch++)
                    ldB(Bf[ch], bbase, (u32)(32 * ntq + 8 * ch), brow_r, bkb_g);

                float c[4][4];
                #pragma unroll
                for (int ch = 0; ch < 4; ch++)
                    { c[ch][0] = 0.f; c[ch][1] = 0.f; c[ch][2] = 0.f; c[ch][3] = 0.f; }
                #pragma unroll
                for (int kt = 0; kt < 4; kt++)
                    #pragma unroll
                    for (int ch = 0; ch < 4; ch++)
                        mma16816(c[ch], Af[kt], Bf[ch][kt]);

                #pragma unroll
                for (int uu = 0; uu < 2; uu++) {
                    const int u = half * 8 + 2 * ntq + uu;
                    const float* d0 = c[2 * uu];       // v 0..7
                    const float* d1 = c[2 * uu + 1];   // v 8..15
                    if (b == 0 || b == 1) {
                        const float* sp = &Sf[b * SF_STR + eoff * SE_STR + u];
                        #pragma unroll
                        for (int e = 0; e < 2; e++) {
                            ull s = splat2(sp[e * 8 * SE_STR]);
                            acc[0][e][0] = fma2(s, pack2(d0[2*e], d0[2*e+1]), acc[0][e][0]);
                            acc[0][e][1] = fma2(s, pack2(d1[2*e], d1[2*e+1]), acc[0][e][1]);
                        }
                    } else if (b == 2) {
                        const float* sp = &Sf[2 * SF_STR + eoff * SE_STR + u];
                        #pragma unroll
                        for (int e = 0; e < 2; e++) {
                            ull s = splat2(sp[e * 8 * SE_STR]);
                            acc[1][e][0] = fma2(s, pack2(d0[2*e], d0[2*e+1]), acc[1][e][0]);
                            acc[1][e][1] = fma2(s, pack2(d1[2*e], d1[2*e+1]), acc[1][e][1]);
                        }
                    } else {
                        #pragma unroll
                        for (int k = 0; k < 3; k++) {
                            const float* sp = &Sf[(3 + k) * SF_STR + eoff * SE_STR + u];
                            #pragma unroll
                            for (int e = 0; e < 2; e++) {
                                ull s = splat2(sp[e * 8 * SE_STR]);
                                acc[2+k][e][0] = fma2(s, pack2(d0[2*e], d0[2*e+1]), acc[2+k][e][0]);
                                acc[2+k][e][1] = fma2(s, pack2(d1[2*e], d1[2*e+1]), acc[2+k][e][1]);
                            }
                        }
                    }
                }
            }
        }

        // ---- epilogue: scatter-add via vector reds ----
        #pragma unroll
        for (int e = 0; e < 2; e++) {
            const int el = eoff + 8 * e;
            const int eg = e_base + el;
            if (eg >= E) continue;
            float* op = out + (size_t)dsts[el] * 64;
            const float k0 = attr[el * 4 + 1];
            const float k1 = attr[el * 4 + 2];
            const float k2 = attr[el * 4 + 3];

            #pragma unroll
            for (int p = 0; p < 2; p++) {
                float m0a, m0b, ta, tb;
                float a0a, a0b, a1a, a1b, a2a, a2b;
                unpack2(acc[0][e][p], m0a, m0b);
                unpack2(acc[1][e][p], ta, tb);
                unpack2(acc[2][e][p], a0a, a0b);
                unpack2(acc[3][e][p], a1a, a1b);
                unpack2(acc[4][e][p], a2a, a2b);
                const int v = 8 * p + 2 * q;
                red2(op + v, SCALE_OUT * m0a, SCALE_OUT * m0b);
                const int base = 16 + 3 * v;
                red2(op + base,     SCALE_OUT * fmaf(k0, ta, a0a), SCALE_OUT * fmaf(k1, ta, a1a));
                red2(op + base + 2, SCALE_OUT * fmaf(k2, ta, a2a), SCALE_OUT * fmaf(k0, tb, a0b));
                red2(op + base + 4, SCALE_OUT * fmaf(k1, tb, a1b), SCALE_OUT * fmaf(k2, tb, a2b));
            }
        }
    }
}

extern "C" void kernel_launch(void* const* d_in, const int* in_sizes, int n_in,
                              void* d_out, int out_size)
{
    const float* x         = (const float*)d_in[0];
    const float* edge_attr = (const float*)d_in[1];
    const float* edge_len  = (const float*)d_in[2];
    const int*   src       = (const int*)d_in[3];
    const int*   dst       = (const int*)d_in[4];
    const float* W1        = (const float*)d_in[5];
    const float* W2        = (const float*)d_in[6];
    const float* L0        = (const float*)d_in[7];
    const float* L1        = (const float*)d_in[8];
    float* out = (float*)d_out;

    const int E = in_sizes[2];
    const int Nnodes = in_sizes[0] / 64;
    const int ntiles = (E + TILE_E - 1) / TILE_E;

    cudaFuncSetAttribute(edge_mma_kernel, cudaFuncAttributeMaxDynamicSharedMemorySize, SMEM_BYTES);

    int nsm = 148;
    cudaDeviceGetAttribute(&nsm, cudaDevAttrMultiProcessorCount, 0);
    int grid = 2 * nsm;
    if (grid > ntiles) grid = ntiles;

    const int sc_blocks = (Nnodes + 255) / 256;
    pre_kernel<<<PREP_BLOCKS + sc_blocks, 256>>>(W2, x, L0, L1, out, Nnodes);
    edge_mma_kernel<<<grid, THREADS, SMEM_BYTES>>>(
        x, edge_attr, edge_len, src, dst, W1, out, E, ntiles);
}